// round 5
// baseline (speedup 1.0000x reference)
#include <cuda_runtime.h>

// Energy distance, B=16, N=M=256, D=128, fp32.
// Per (batch, dim): 2-warp cooperative register bitonic sort (4 elems/thread),
// closed-form pairwise L1 sums via prefix sums + binary search.

#define EB 16
#define EN 256
#define ED 128
#define COLS 4
#define FULL_MASK 0xFFFFFFFFu

// phys(i) = i + i/4: for i = 4*tid + r this is 5*tid + r -> conflict-free.
__device__ __forceinline__ int phys(int i) { return i + (i >> 2); }

__device__ __forceinline__ void colbar(int col) {
    asm volatile("bar.sync %0, 64;" :: "r"(col + 1) : "memory");
}

__global__ void ed_init_out(float* out) {
    if (threadIdx.x < EB) out[threadIdx.x] = 0.0f;
}

__global__ __launch_bounds__(256) void ed_kernel(
    const float* __restrict__ x1,
    const float* __restrict__ x2,
    float* __restrict__ out)
{
    __shared__ float sa[COLS][324];   // x1 stage -> exchange v1 -> exclusive prefix of sorted v2
    __shared__ float sb[COLS][324];   // x2 stage -> exchange v2 -> sorted v2 (+INF sentinel)
    __shared__ float wsum[COLS][2];
    __shared__ float cres[COLS][2];

    const int b     = blockIdx.y;
    const int d0    = blockIdx.x * COLS;
    const int t     = threadIdx.x;
    const int lane  = t & 31;
    const int col   = t >> 6;          // 0..3 : column (dim) within block
    const int wc    = (t >> 5) & 1;    // warp-in-column
    const int tid_c = t & 63;          // thread-in-column

    // ---- Stage: one float4 per input per thread (sample = t, dims d0..d0+3) ----
    const size_t off = ((size_t)(b * EN + t)) * ED + d0;
    const float4 a4 = *reinterpret_cast<const float4*>(x1 + off);
    const float4 b4 = *reinterpret_cast<const float4*>(x2 + off);
    const int ph = phys(t);
    sa[0][ph] = a4.x; sa[1][ph] = a4.y; sa[2][ph] = a4.z; sa[3][ph] = a4.w;
    sb[0][ph] = b4.x; sb[1][ph] = b4.y; sb[2][ph] = b4.z; sb[3][ph] = b4.w;
    __syncthreads();

    // ---- Load column slice into registers: i = 4*tid_c + r ----
    const int base = 5 * tid_c;
    float v1[4], v2[4];
    #pragma unroll
    for (int r = 0; r < 4; r++) { v1[r] = sa[col][base + r]; v2[r] = sb[col][base + r]; }

    // ---- Interleaved bitonic sort of v1 and v2 (ascending over i) ----
    #pragma unroll
    for (int k = 2; k <= EN; k <<= 1) {
        #pragma unroll
        for (int j = k >> 1; j > 0; j >>= 1) {
            if (j >= 128) {
                // cross-warp stage (only k=256, j=128): smem exchange.
                // asc == true here; lower warp keeps min, upper keeps max.
                #pragma unroll
                for (int r = 0; r < 4; r++) { sa[col][base + r] = v1[r]; sb[col][base + r] = v2[r]; }
                colbar(col);
                const int pbase = 5 * (tid_c ^ 32);
                #pragma unroll
                for (int r = 0; r < 4; r++) {
                    const float u1 = sa[col][pbase + r];
                    const float u2 = sb[col][pbase + r];
                    v1[r] = wc ? fmaxf(v1[r], u1) : fminf(v1[r], u1);
                    v2[r] = wc ? fmaxf(v2[r], u2) : fminf(v2[r], u2);
                }
                // next write to sa/sb is the writeback, ordered by the wsum colbar
            } else if (j >= 4) {
                const int m = j >> 2;
                const bool asc = (((tid_c << 2) & k) == 0);
                const bool keepMin = (((lane & m) != 0) != asc);
                #pragma unroll
                for (int r = 0; r < 4; r++) {
                    const float u1 = __shfl_xor_sync(FULL_MASK, v1[r], m);
                    const float u2 = __shfl_xor_sync(FULL_MASK, v2[r], m);
                    v1[r] = keepMin ? fminf(v1[r], u1) : fmaxf(v1[r], u1);
                    v2[r] = keepMin ? fminf(v2[r], u2) : fmaxf(v2[r], u2);
                }
            } else {
                #pragma unroll
                for (int r = 0; r < 4; r++) {
                    if ((r & j) == 0) {
                        const int q = r | j;
                        const bool asc = ((((tid_c << 2) | r) & k) == 0);
                        float a = v1[r], c = v1[q];
                        float lo_ = fminf(a, c), hi_ = fmaxf(a, c);
                        v1[r] = asc ? lo_ : hi_;  v1[q] = asc ? hi_ : lo_;
                        a = v2[r]; c = v2[q];
                        lo_ = fminf(a, c); hi_ = fmaxf(a, c);
                        v2[r] = asc ? lo_ : hi_;  v2[q] = asc ? hi_ : lo_;
                    }
                }
            }
        }
    }

    // ---- Prefix sums of sorted v2 across the 64-thread column ----
    const float p0 = v2[0];
    const float p1 = p0 + v2[1];
    const float p2 = p1 + v2[2];
    const float p3 = p2 + v2[3];
    float incl = p3;
    #pragma unroll
    for (int o = 1; o < 32; o <<= 1) {
        const float nb = __shfl_up_sync(FULL_MASK, incl, o);
        if (lane >= o) incl += nb;
    }
    if (lane == 31) wsum[col][wc] = incl;
    colbar(col);
    const float w0   = wsum[col][0];
    const float Ptot = w0 + wsum[col][1];
    const float excl = incl - p3 + (wc ? w0 : 0.0f);

    // ---- Writeback: sorted v2 -> sb, exclusive prefix -> sa ----
    sb[col][base + 0] = v2[0]; sb[col][base + 1] = v2[1];
    sb[col][base + 2] = v2[2]; sb[col][base + 3] = v2[3];
    sa[col][base + 0] = excl;       sa[col][base + 1] = excl + p0;
    sa[col][base + 2] = excl + p1;  sa[col][base + 3] = excl + p2;
    if (tid_c == 63) {
        sa[col][320] = Ptot;                         // pb[256] (phys(256)=320)
        sb[col][320] = __int_as_float(0x7f800000);   // +INF sentinel: search top-out
    }
    colbar(col);

    // ---- Cross term (binary search) + same-term closed form ----
    float acc = 0.0f;
    #pragma unroll
    for (int r = 0; r < 4; r++) {
        const float a = v1[r];
        int lo = 0, hi = EN;
        #pragma unroll
        for (int s = 0; s < 9; s++) {
            const int mid = (lo + hi) >> 1;
            const bool le = (sb[col][phys(mid)] <= a);
            lo = le ? mid + 1 : lo;
            hi = le ? hi : mid;
        }
        const float cross = a * (float)(2 * lo - EN) + Ptot - 2.0f * sa[col][phys(lo)];
        const int i = (tid_c << 2) + r;
        const float wt = (float)(2 * i - (EN - 1));
        acc += cross - wt * (v1[r] + v2[r]);
    }

    // ---- Reduce: warp, then pair of warps, then one atomic per column ----
    #pragma unroll
    for (int o = 16; o; o >>= 1)
        acc += __shfl_xor_sync(FULL_MASK, acc, o);
    if (lane == 0) cres[col][wc] = acc;
    colbar(col);
    if (tid_c == 0)
        atomicAdd(out + b, (cres[col][0] + cres[col][1]) * (1.0f / (float)(EN * EN)));
}

extern "C" void kernel_launch(void* const* d_in, const int* in_sizes, int n_in,
                              void* d_out, int out_size)
{
    const float* x1 = (const float*)d_in[0];
    const float* x2 = (const float*)d_in[1];
    float* out = (float*)d_out;

    ed_init_out<<<1, 32>>>(out);
    dim3 grid(ED / COLS, EB);   // (32, 16): 4 dims/block, 2 warps per dim
    ed_kernel<<<grid, 256>>>(x1, x2, out);
}